// round 16
// baseline (speedup 1.0000x reference)
#include <cuda_runtime.h>
#include <cuda_fp16.h>
#include <math.h>

// NeuralNDCG, N=4096. Persistent kernel, 296 blocks (2/SM) x 512 threads.
// mat_t = diag(R) U diag(C'). R16: the block's U slab (14 rows x 8 cols/thread,
// e5m2) lives in 28 REGISTERS for all 50 iterations; the block's U^T slab
// lives in 56KB SHARED MEMORY (written directly by phase 2 -- the col sweep
// only ever reads the block's own U^T rows, so no global U^T array at all).
// Steady-state global traffic per iteration: one C' vector read, one R vector
// read, 14-float R and C writes. Two tree grid barriers per iteration.

#define NNV 4096
#define NBLK 296
#define TPB 512
#define ROWS 14
#define EPSF 1e-10f
#define ITERS 50
#define SMEM_BYTES (ROWS * TPB * 8)          // 57344: U^T slab (uint2/thread/row)

__device__ unsigned char g_U[(size_t)NNV * NNV];   // 16 MB e5m2 (read once)
__device__ float g_Bv[NNV], g_mv[NNV], g_R[NNV], g_Cp[NNV];
__device__ float g_rowdcg[NNV];
__device__ float g_idcgPart[NBLK];
__device__ unsigned g_leaf[37 * 32];
__device__ unsigned g_root;
__device__ volatile unsigned g_gen;

__device__ __forceinline__ unsigned grid_arrive(int bid, int tid) {
    __syncthreads();
    unsigned mygen = 0;
    if (tid == 0) {
        __threadfence();
        mygen = g_gen;
        unsigned l = (unsigned)(bid >> 3) * 32;       // 37 leaves x 8 blocks
        if (atomicAdd(&g_leaf[l], 1u) == 7) {
            atomicExch(&g_leaf[l], 0u);
            if (atomicAdd(&g_root, 1u) == 36) {
                atomicExch(&g_root, 0u);
                __threadfence();
                g_gen = mygen + 1;
            }
        }
    }
    return mygen;
}
__device__ __forceinline__ void grid_wait(unsigned mygen, int tid) {
    if (tid == 0) {
        while (g_gen == mygen) { }
        __threadfence();
    }
    __syncthreads();
}
__device__ __forceinline__ void grid_barrier(int bid, int tid) {
    unsigned g = grid_arrive(bid, tid);
    grid_wait(g, tid);
}

__device__ __forceinline__ float wredsum(float v) {
    #pragma unroll
    for (int o = 16; o > 0; o >>= 1) v += __shfl_xor_sync(0xffffffffu, v, o);
    return v;
}
__device__ __forceinline__ float wredmax(float v) {
    #pragma unroll
    for (int o = 16; o > 0; o >>= 1) v = fmaxf(v, __shfl_xor_sync(0xffffffffu, v, o));
    return v;
}

__device__ __forceinline__ unsigned pack4_e5m2(float a0, float a1, float a2, float a3) {
    unsigned short lo, hi;
    asm("cvt.rn.satfinite.e5m2x2.f32 %0, %1, %2;" : "=h"(lo) : "f"(a1), "f"(a0));
    asm("cvt.rn.satfinite.e5m2x2.f32 %0, %1, %2;" : "=h"(hi) : "f"(a3), "f"(a2));
    return (unsigned)lo | ((unsigned)hi << 16);
}

__device__ __forceinline__ float dot8f8(uint2 q, const float* w) {
    float d = 0.0f;
    unsigned p;
    float2 f;
    p = __byte_perm(q.x, 0, 0x1404);                  // e5m2->f16 exact byte shift
    f = __half22float2(*(__half2*)&p);
    d = fmaf(f.x, w[0], d); d = fmaf(f.y, w[1], d);
    p = __byte_perm(q.x, 0, 0x3424);
    f = __half22float2(*(__half2*)&p);
    d = fmaf(f.x, w[2], d); d = fmaf(f.y, w[3], d);
    p = __byte_perm(q.y, 0, 0x1404);
    f = __half22float2(*(__half2*)&p);
    d = fmaf(f.x, w[4], d); d = fmaf(f.y, w[5], d);
    p = __byte_perm(q.y, 0, 0x3424);
    f = __half22float2(*(__half2*)&p);
    d = fmaf(f.x, w[6], d); d = fmaf(f.y, w[7], d);
    return d;
}

__global__ void __launch_bounds__(TPB, 2)
ndcg_kernel(const float* __restrict__ pred, const float* __restrict__ target,
            float* __restrict__ out)
{
    extern __shared__ __align__(16) char dsm[];
    uint2* sUT = (uint2*)dsm;                          // [ROWS][TPB] after build
    float* p_stage = (float*)dsm;                      // phases 0-1 alias
    float* t_stage = p_stage + NNV;
    __shared__ float s_pb[ROWS * 17];
    __shared__ float s_pd[ROWS * 17];
    __shared__ float s_red[32];

    const int tid = threadIdx.x, bid = blockIdx.x;
    const int wid = tid >> 5, lane = tid & 31;
    const int start = bid * ROWS;
    const int myi = start + wid;
    const bool vown = (wid < ROWS) && (myi < NNV);
    const bool fown = (tid < ROWS) && (start + tid < NNV);
    float R_own = 0.0f, C_own = 0.0f;
    uint2 qU[ROWS];                                    // block's U slab, e5m2

    // ================= PHASE 0: B[j], ideal DCG ============================
    for (int k = tid; k < NNV; k += TPB) { p_stage[k] = pred[k]; t_stage[k] = target[k]; }
    if (wid < ROWS && lane == 0) s_red[wid] = 0.0f;
    __syncthreads();
    if (vown) {
        float pj = p_stage[myi], tj = t_stage[myi];
        float acc = 0.0f; int trank = 0;
        #pragma unroll 4
        for (int k = 0; k < 128; k++) {
            acc += fabsf(pj - p_stage[k * 32 + lane]);
            trank += (t_stage[k * 32 + lane] > tj);
        }
        acc = wredsum(acc);
        #pragma unroll
        for (int o = 16; o > 0; o >>= 1) trank += __shfl_xor_sync(0xffffffffu, trank, o);
        if (lane == 0) {
            g_Bv[myi] = acc;
            s_red[wid] = (exp2f(tj) - 1.0f) / log2f((float)trank + 2.0f);
        }
    }
    __syncthreads();
    if (tid == 0) {
        float s = 0.0f;
        for (int k = 0; k < ROWS; k++) s += s_red[k];
        g_idcgPart[bid] = s;
    }
    grid_barrier(bid, tid);

    // ================= PHASE 1: build U rows (e5m2 -> global), m_i, R0 =====
    for (int k = tid; k < NNV; k += TPB) t_stage[k] = __ldcg(&g_Bv[k]);
    __syncthreads();
    if (vown) {
        const int i = myi;
        const float ci = (float)(NNV - 1 - 2 * i);
        float m = -INFINITY;
        for (int c = 0; c < 16; c++) {
            int j0 = (c * 32 + lane) * 8;
            #pragma unroll
            for (int mm = 0; mm < 8; mm++)
                m = fmaxf(m, fmaf(ci, p_stage[j0 + mm], -t_stage[j0 + mm]));
        }
        m = wredmax(m);
        float z = 0.0f;
        uint2* rq = reinterpret_cast<uint2*>(g_U + (size_t)i * NNV);
        for (int c = 0; c < 16; c++) {
            int j0 = (c * 32 + lane) * 8;
            float e[8];
            #pragma unroll
            for (int mm = 0; mm < 8; mm++) {
                e[mm] = __expf(fmaf(ci, p_stage[j0 + mm], -t_stage[j0 + mm]) - m);
                z += e[mm];
            }
            uint2 q;
            q.x = pack4_e5m2(e[0], e[1], e[2], e[3]);
            q.y = pack4_e5m2(e[4], e[5], e[6], e[7]);
            rq[c * 32 + lane] = q;
        }
        z = wredsum(z);
        if (lane == 0) { g_mv[i] = m; g_R[i] = 1.0f / z; }
    }
    grid_barrier(bid, tid);                            // staging dead after this

    // ================= PHASE 2: build U^T slab in SMEM + a0 -> C'1 =========
    if (fown) R_own = __ldcg(&g_R[start + tid]);
    {
        float m_r[8], r0_r[8], ci_r[8];
        {
            const float4* mp = (const float4*)(g_mv + tid * 8);
            const float4* rp = (const float4*)(g_R + tid * 8);
            float4 m0 = __ldcg(mp), m1 = __ldcg(mp + 1);
            float4 r0 = __ldcg(rp), r1 = __ldcg(rp + 1);
            m_r[0]=m0.x; m_r[1]=m0.y; m_r[2]=m0.z; m_r[3]=m0.w;
            m_r[4]=m1.x; m_r[5]=m1.y; m_r[6]=m1.z; m_r[7]=m1.w;
            r0_r[0]=r0.x; r0_r[1]=r0.y; r0_r[2]=r0.z; r0_r[3]=r0.w;
            r0_r[4]=r1.x; r0_r[5]=r1.y; r0_r[6]=r1.z; r0_r[7]=r1.w;
        }
        #pragma unroll
        for (int mm = 0; mm < 8; mm++)
            ci_r[mm] = (float)(NNV - 1 - 2 * (tid * 8 + mm));
        #pragma unroll
        for (int r = 0; r < ROWS; r++) {
            int j = min(start + r, NNV - 1);           // clamp: duplicate row, unused
            float pj = __ldg(&pred[j]);
            float Bj = __ldcg(&g_Bv[j]);
            float e[8], d = 0.0f;
            #pragma unroll
            for (int mm = 0; mm < 8; mm++) {
                e[mm] = __expf(fmaf(ci_r[mm], pj, -Bj) - m_r[mm]);
                d = fmaf(r0_r[mm], e[mm], d);
            }
            uint2 q;
            q.x = pack4_e5m2(e[0], e[1], e[2], e[3]);
            q.y = pack4_e5m2(e[4], e[5], e[6], e[7]);
            sUT[r * TPB + tid] = q;                    // own U^T rows -> smem only
            d = wredsum(d);
            if (lane == 0) s_pb[r * 17 + wid] = d;
        }
        __syncthreads();
        if (fown) {
            float a = 0.0f;
            #pragma unroll
            for (int k = 0; k < 16; k++) a += s_pb[tid * 17 + k];
            C_own = 1.0f / fmaxf(a, EPSF);             // C0 = 1
            g_Cp[start + tid] = C_own;
        }
    }
    // barrier; load U slab into registers during the wait (own rows, L2-hot)
    {
        unsigned g = grid_arrive(bid, tid);
        #pragma unroll
        for (int r = 0; r < ROWS; r++)
            qU[r] = ((const uint2*)(g_U + (size_t)min(start + r, NNV - 1) * NNV))[tid];
        grid_wait(g, tid);
    }

    // ================= 50 SINKHORN ITERATIONS ==============================
    for (int t = 0; t < ITERS; t++) {
        const bool last = (t == ITERS - 1);

        // fresh C' for my 8 columns
        float cs_r[8];
        {
            const float4* cp = (const float4*)(g_Cp + tid * 8);
            float4 c0 = __ldcg(cp), c1 = __ldcg(cp + 1);
            cs_r[0]=c0.x; cs_r[1]=c0.y; cs_r[2]=c0.z; cs_r[3]=c0.w;
            cs_r[4]=c1.x; cs_r[5]=c1.y; cs_r[6]=c1.z; cs_r[7]=c1.w;
        }

        if (!last) {
            // ---- row sweep: pure ALU from register slab ----
            #pragma unroll
            for (int r = 0; r < ROWS; r++) {
                float d = wredsum(dot8f8(qU[r], cs_r));
                if (lane == 0) s_pb[r * 17 + wid] = d;
            }
            __syncthreads();
            if (fown) {
                float b = 0.0f;
                #pragma unroll
                for (int k = 0; k < 16; k++) b += s_pb[tid * 17 + k];
                float Rn = R_own / fmaxf(R_own * b, EPSF);
                R_own = Rn;
                g_R[start + tid] = Rn;
            }
            grid_barrier(bid, tid);

            // ---- col sweep: U^T slab from smem ----
            float rs_r[8];
            {
                const float4* rp = (const float4*)(g_R + tid * 8);
                float4 r0 = __ldcg(rp), r1 = __ldcg(rp + 1);
                rs_r[0]=r0.x; rs_r[1]=r0.y; rs_r[2]=r0.z; rs_r[3]=r0.w;
                rs_r[4]=r1.x; rs_r[5]=r1.y; rs_r[6]=r1.z; rs_r[7]=r1.w;
            }
            #pragma unroll
            for (int r = 0; r < ROWS; r++) {
                float d = wredsum(dot8f8(sUT[r * TPB + tid], rs_r));
                if (lane == 0) s_pb[r * 17 + wid] = d;
            }
            __syncthreads();
            if (fown) {
                float a = 0.0f;
                #pragma unroll
                for (int k = 0; k < 16; k++) a += s_pb[tid * 17 + k];
                float Cn = C_own / fmaxf(C_own * a, EPSF);
                C_own = Cn;
                g_Cp[start + tid] = Cn;
            }
            grid_barrier(bid, tid);
        } else {
            // ---- last iteration: row sweep + DCG fold (register slab) ----
            float gs_r[8];
            #pragma unroll
            for (int mm = 0; mm < 8; mm++)
                gs_r[mm] = cs_r[mm] * (exp2f(target[tid * 8 + mm]) - 1.0f);
            #pragma unroll
            for (int r = 0; r < ROWS; r++) {
                float d1 = wredsum(dot8f8(qU[r], cs_r));
                float d2 = wredsum(dot8f8(qU[r], gs_r));
                if (lane == 0) { s_pb[r * 17 + wid] = d1; s_pd[r * 17 + wid] = d2; }
            }
            __syncthreads();
            if (fown) {
                int i = start + tid;
                float b = 0.0f, d = 0.0f;
                #pragma unroll
                for (int k = 0; k < 16; k++) {
                    b += s_pb[tid * 17 + k];
                    d += s_pd[tid * 17 + k];
                }
                float Rn = R_own / fmaxf(R_own * b, EPSF);
                g_rowdcg[i] = Rn * d / log2f((float)i + 2.0f);
            }
            grid_barrier(bid, tid);
        }
    }

    // ================= FINAL ==============================================
    if (bid == 0) {
        float part = 0.0f;
        #pragma unroll
        for (int k = 0; k < 8; k++) part += __ldcg(&g_rowdcg[tid * 8 + k]);
        part = wredsum(part);
        if (lane == 0) s_red[wid] = part;
        float ip = (tid < NBLK) ? __ldcg(&g_idcgPart[tid]) : 0.0f;
        ip = wredsum(ip);
        if (lane == 0) s_red[16 + wid] = ip;
        __syncthreads();
        if (tid == 0) {
            float dcg = 0.0f, idcg = 0.0f;
            for (int k = 0; k < 16; k++) { dcg += s_red[k]; idcg += s_red[16 + k]; }
            out[0] = -(dcg / (idcg + 1e-8f));
        }
    }
}

extern "C" void kernel_launch(void* const* d_in, const int* in_sizes, int n_in,
                              void* d_out, int out_size) {
    const float* pred   = (const float*)d_in[0];
    const float* target = (const float*)d_in[1];
    float* out = (float*)d_out;
    cudaFuncSetAttribute(ndcg_kernel, cudaFuncAttributeMaxDynamicSharedMemorySize,
                         SMEM_BYTES);
    ndcg_kernel<<<NBLK, TPB, SMEM_BYTES>>>(pred, target, out);
}

// round 17
// speedup vs baseline: 1.1720x; 1.1720x over previous
#include <cuda_runtime.h>
#include <cuda_fp16.h>
#include <math.h>

// NeuralNDCG, N=4096. Persistent kernel, 296 blocks (2/SM) x 512 threads.
// mat_t = diag(R) U diag(C'); U in FP8 E5M2 global (16MB, L2-resident,
// read-only). R17 = R15 + smem U^T: the block's U^T slab (14 rows, e5m2) is
// written by phase 2 DIRECTLY into 56KB dynamic smem (col sweep only ever
// reads the block's own U^T rows -> no global U^T array, LDS latency).
// Row sweep keeps R15's batched global loads with cross-barrier group-0
// preload (no register slab -> no spills). Two tree barriers per iteration.

#define NNV 4096
#define NBLK 296
#define TPB 512
#define ROWS 14
#define EPSF 1e-10f
#define ITERS 50
#define SMEM_BYTES (ROWS * TPB * 8)          // 57344: U^T slab (uint2/thread/row)

__device__ unsigned char g_U[(size_t)NNV * NNV];   // 16 MB e5m2
__device__ float g_Bv[NNV], g_mv[NNV], g_R[NNV], g_Cp[NNV];
__device__ float g_rowdcg[NNV];
__device__ float g_idcgPart[NBLK];
__device__ unsigned g_leaf[37 * 32];
__device__ unsigned g_root;
__device__ volatile unsigned g_gen;

__device__ __forceinline__ unsigned grid_arrive(int bid, int tid) {
    __syncthreads();
    unsigned mygen = 0;
    if (tid == 0) {
        __threadfence();
        mygen = g_gen;
        unsigned l = (unsigned)(bid >> 3) * 32;       // 37 leaves x 8 blocks
        if (atomicAdd(&g_leaf[l], 1u) == 7) {
            atomicExch(&g_leaf[l], 0u);
            if (atomicAdd(&g_root, 1u) == 36) {
                atomicExch(&g_root, 0u);
                __threadfence();
                g_gen = mygen + 1;
            }
        }
    }
    return mygen;
}
__device__ __forceinline__ void grid_wait(unsigned mygen, int tid) {
    if (tid == 0) {
        while (g_gen == mygen) { }                    // tight spin
        __threadfence();
    }
    __syncthreads();
}
__device__ __forceinline__ void grid_barrier(int bid, int tid) {
    unsigned g = grid_arrive(bid, tid);
    grid_wait(g, tid);
}

__device__ __forceinline__ float wredsum(float v) {
    #pragma unroll
    for (int o = 16; o > 0; o >>= 1) v += __shfl_xor_sync(0xffffffffu, v, o);
    return v;
}
__device__ __forceinline__ float wredmax(float v) {
    #pragma unroll
    for (int o = 16; o > 0; o >>= 1) v = fmaxf(v, __shfl_xor_sync(0xffffffffu, v, o));
    return v;
}

__device__ __forceinline__ unsigned pack4_e5m2(float a0, float a1, float a2, float a3) {
    unsigned short lo, hi;
    asm("cvt.rn.satfinite.e5m2x2.f32 %0, %1, %2;" : "=h"(lo) : "f"(a1), "f"(a0));
    asm("cvt.rn.satfinite.e5m2x2.f32 %0, %1, %2;" : "=h"(hi) : "f"(a3), "f"(a2));
    return (unsigned)lo | ((unsigned)hi << 16);
}

__device__ __forceinline__ float dot8f8(uint2 q, const float* w) {
    float d = 0.0f;
    unsigned p;
    float2 f;
    p = __byte_perm(q.x, 0, 0x1404);                  // e5m2->f16 exact byte shift
    f = __half22float2(*(__half2*)&p);
    d = fmaf(f.x, w[0], d); d = fmaf(f.y, w[1], d);
    p = __byte_perm(q.x, 0, 0x3424);
    f = __half22float2(*(__half2*)&p);
    d = fmaf(f.x, w[2], d); d = fmaf(f.y, w[3], d);
    p = __byte_perm(q.y, 0, 0x1404);
    f = __half22float2(*(__half2*)&p);
    d = fmaf(f.x, w[4], d); d = fmaf(f.y, w[5], d);
    p = __byte_perm(q.y, 0, 0x3424);
    f = __half22float2(*(__half2*)&p);
    d = fmaf(f.x, w[6], d); d = fmaf(f.y, w[7], d);
    return d;
}

__global__ void __launch_bounds__(TPB, 2)
ndcg_kernel(const float* __restrict__ pred, const float* __restrict__ target,
            float* __restrict__ out)
{
    extern __shared__ __align__(16) char dsm[];
    uint2* sUT = (uint2*)dsm;                          // [ROWS][TPB] after build
    float* p_stage = (float*)dsm;                      // phases 0-1 alias
    float* t_stage = p_stage + NNV;
    __shared__ float s_pb[ROWS * 17];
    __shared__ float s_pd[ROWS * 17];
    __shared__ float s_red[32];

    const int tid = threadIdx.x, bid = blockIdx.x;
    const int wid = tid >> 5, lane = tid & 31;
    const int start = bid * ROWS;
    const int myi = start + wid;
    const bool vown = (wid < ROWS) && (myi < NNV);
    const bool fown = (tid < ROWS) && (start + tid < NNV);
    float R_own = 0.0f, C_own = 0.0f;
    uint2 qpre[5];

    // ================= PHASE 0: B[j], ideal DCG ============================
    for (int k = tid; k < NNV; k += TPB) { p_stage[k] = pred[k]; t_stage[k] = target[k]; }
    if (wid < ROWS && lane == 0) s_red[wid] = 0.0f;
    __syncthreads();
    if (vown) {
        float pj = p_stage[myi], tj = t_stage[myi];
        float acc = 0.0f; int trank = 0;
        #pragma unroll 4
        for (int k = 0; k < 128; k++) {
            acc += fabsf(pj - p_stage[k * 32 + lane]);
            trank += (t_stage[k * 32 + lane] > tj);
        }
        acc = wredsum(acc);
        #pragma unroll
        for (int o = 16; o > 0; o >>= 1) trank += __shfl_xor_sync(0xffffffffu, trank, o);
        if (lane == 0) {
            g_Bv[myi] = acc;
            s_red[wid] = (exp2f(tj) - 1.0f) / log2f((float)trank + 2.0f);
        }
    }
    __syncthreads();
    if (tid == 0) {
        float s = 0.0f;
        for (int k = 0; k < ROWS; k++) s += s_red[k];
        g_idcgPart[bid] = s;
    }
    grid_barrier(bid, tid);

    // ================= PHASE 1: build U rows (e5m2 -> global), m_i, R0 =====
    for (int k = tid; k < NNV; k += TPB) t_stage[k] = __ldcg(&g_Bv[k]);
    __syncthreads();
    if (vown) {
        const int i = myi;
        const float ci = (float)(NNV - 1 - 2 * i);
        float m = -INFINITY;
        for (int c = 0; c < 16; c++) {
            int j0 = (c * 32 + lane) * 8;
            #pragma unroll
            for (int mm = 0; mm < 8; mm++)
                m = fmaxf(m, fmaf(ci, p_stage[j0 + mm], -t_stage[j0 + mm]));
        }
        m = wredmax(m);
        float z = 0.0f;
        uint2* rq = reinterpret_cast<uint2*>(g_U + (size_t)i * NNV);
        for (int c = 0; c < 16; c++) {
            int j0 = (c * 32 + lane) * 8;
            float e[8];
            #pragma unroll
            for (int mm = 0; mm < 8; mm++) {
                e[mm] = __expf(fmaf(ci, p_stage[j0 + mm], -t_stage[j0 + mm]) - m);
                z += e[mm];
            }
            uint2 q;
            q.x = pack4_e5m2(e[0], e[1], e[2], e[3]);
            q.y = pack4_e5m2(e[4], e[5], e[6], e[7]);
            rq[c * 32 + lane] = q;
        }
        z = wredsum(z);
        if (lane == 0) { g_mv[i] = m; g_R[i] = 1.0f / z; }
    }
    grid_barrier(bid, tid);                            // staging dead after this

    // ================= PHASE 2: U^T slab -> SMEM + a0 -> C'1 ===============
    if (fown) R_own = __ldcg(&g_R[start + tid]);
    {
        float m_r[8], r0_r[8], ci_r[8];
        {
            const float4* mp = (const float4*)(g_mv + tid * 8);
            const float4* rp = (const float4*)(g_R + tid * 8);
            float4 m0 = __ldcg(mp), m1 = __ldcg(mp + 1);
            float4 r0 = __ldcg(rp), r1 = __ldcg(rp + 1);
            m_r[0]=m0.x; m_r[1]=m0.y; m_r[2]=m0.z; m_r[3]=m0.w;
            m_r[4]=m1.x; m_r[5]=m1.y; m_r[6]=m1.z; m_r[7]=m1.w;
            r0_r[0]=r0.x; r0_r[1]=r0.y; r0_r[2]=r0.z; r0_r[3]=r0.w;
            r0_r[4]=r1.x; r0_r[5]=r1.y; r0_r[6]=r1.z; r0_r[7]=r1.w;
        }
        #pragma unroll
        for (int mm = 0; mm < 8; mm++)
            ci_r[mm] = (float)(NNV - 1 - 2 * (tid * 8 + mm));
        #pragma unroll
        for (int r = 0; r < ROWS; r++) {
            int j = min(start + r, NNV - 1);           // clamp row: written, unused
            float pj = __ldg(&pred[j]);                // scalar broadcast loads
            float Bj = __ldcg(&g_Bv[j]);
            float e[8], d = 0.0f;
            #pragma unroll
            for (int mm = 0; mm < 8; mm++) {
                e[mm] = __expf(fmaf(ci_r[mm], pj, -Bj) - m_r[mm]);
                d = fmaf(r0_r[mm], e[mm], d);
            }
            uint2 q;
            q.x = pack4_e5m2(e[0], e[1], e[2], e[3]);
            q.y = pack4_e5m2(e[4], e[5], e[6], e[7]);
            sUT[r * TPB + tid] = q;                    // own U^T rows: smem only
            d = wredsum(d);
            if (lane == 0) s_pb[r * 17 + wid] = d;
        }
        __syncthreads();
        if (fown) {
            float a = 0.0f;
            #pragma unroll
            for (int k = 0; k < 16; k++) a += s_pb[tid * 17 + k];
            C_own = 1.0f / fmaxf(a, EPSF);             // C0 = 1
            g_Cp[start + tid] = C_own;
        }
    }
    // barrier with row-group-0 preload for iteration 0
    {
        unsigned g = grid_arrive(bid, tid);
        #pragma unroll
        for (int b = 0; b < 5; b++)
            qpre[b] = ((const uint2*)(g_U + (size_t)min(start + b, NNV - 1) * NNV))[tid];
        grid_wait(g, tid);
    }

    // ================= 50 SINKHORN ITERATIONS ==============================
    for (int t = 0; t < ITERS; t++) {
        const bool last = (t == ITERS - 1);

        // fresh C' for my 8 columns
        float cs_r[8];
        {
            const float4* cp = (const float4*)(g_Cp + tid * 8);
            float4 c0 = __ldcg(cp), c1 = __ldcg(cp + 1);
            cs_r[0]=c0.x; cs_r[1]=c0.y; cs_r[2]=c0.z; cs_r[3]=c0.w;
            cs_r[4]=c1.x; cs_r[5]=c1.y; cs_r[6]=c1.z; cs_r[7]=c1.w;
        }

        if (!last) {
            // ---- row sweep over U: group 0 preloaded, groups 1,2 streamed ----
            #pragma unroll
            for (int b = 0; b < 5; b++) {
                float d = wredsum(dot8f8(qpre[b], cs_r));
                if (lane == 0) s_pb[b * 17 + wid] = d;
            }
            #pragma unroll
            for (int g = 1; g < 3; g++) {
                const int r0 = g * 5, B = (g < 2) ? 5 : 4;
                uint2 q[5];
                #pragma unroll
                for (int b = 0; b < 5; b++) if (b < B)
                    q[b] = ((const uint2*)(g_U + (size_t)min(start + r0 + b, NNV - 1) * NNV))[tid];
                #pragma unroll
                for (int b = 0; b < 5; b++) if (b < B) {
                    float d = wredsum(dot8f8(q[b], cs_r));
                    if (lane == 0) s_pb[(r0 + b) * 17 + wid] = d;
                }
            }
            __syncthreads();
            if (fown) {
                float b = 0.0f;
                #pragma unroll
                for (int k = 0; k < 16; k++) b += s_pb[tid * 17 + k];
                float Rn = R_own / fmaxf(R_own * b, EPSF);
                R_own = Rn;
                g_R[start + tid] = Rn;
            }
            grid_barrier(bid, tid);

            // ---- col sweep: U^T slab from smem (LDS latency) ----
            float rs_r[8];
            {
                const float4* rp = (const float4*)(g_R + tid * 8);
                float4 r0 = __ldcg(rp), r1 = __ldcg(rp + 1);
                rs_r[0]=r0.x; rs_r[1]=r0.y; rs_r[2]=r0.z; rs_r[3]=r0.w;
                rs_r[4]=r1.x; rs_r[5]=r1.y; rs_r[6]=r1.z; rs_r[7]=r1.w;
            }
            #pragma unroll
            for (int r = 0; r < ROWS; r++) {
                float d = wredsum(dot8f8(sUT[r * TPB + tid], rs_r));
                if (lane == 0) s_pb[r * 17 + wid] = d;
            }
            __syncthreads();
            if (fown) {
                float a = 0.0f;
                #pragma unroll
                for (int k = 0; k < 16; k++) a += s_pb[tid * 17 + k];
                float Cn = C_own / fmaxf(C_own * a, EPSF);
                C_own = Cn;
                g_Cp[start + tid] = Cn;
            }
            // end barrier: preload next iteration's row-sweep group 0
            {
                unsigned g = grid_arrive(bid, tid);
                #pragma unroll
                for (int b = 0; b < 5; b++)
                    qpre[b] = ((const uint2*)(g_U + (size_t)min(start + b, NNV - 1) * NNV))[tid];
                grid_wait(g, tid);
            }
        } else {
            // ---- last iteration: row sweep + DCG fold ----
            float gs_r[8];
            #pragma unroll
            for (int mm = 0; mm < 8; mm++)
                gs_r[mm] = cs_r[mm] * (exp2f(target[tid * 8 + mm]) - 1.0f);
            #pragma unroll
            for (int b = 0; b < 5; b++) {
                float d1 = wredsum(dot8f8(qpre[b], cs_r));
                float d2 = wredsum(dot8f8(qpre[b], gs_r));
                if (lane == 0) { s_pb[b * 17 + wid] = d1; s_pd[b * 17 + wid] = d2; }
            }
            #pragma unroll
            for (int g = 1; g < 3; g++) {
                const int r0 = g * 5, B = (g < 2) ? 5 : 4;
                uint2 q[5];
                #pragma unroll
                for (int b = 0; b < 5; b++) if (b < B)
                    q[b] = ((const uint2*)(g_U + (size_t)min(start + r0 + b, NNV - 1) * NNV))[tid];
                #pragma unroll
                for (int b = 0; b < 5; b++) if (b < B) {
                    float d1 = wredsum(dot8f8(q[b], cs_r));
                    float d2 = wredsum(dot8f8(q[b], gs_r));
                    if (lane == 0) {
                        s_pb[(r0 + b) * 17 + wid] = d1;
                        s_pd[(r0 + b) * 17 + wid] = d2;
                    }
                }
            }
            __syncthreads();
            if (fown) {
                int i = start + tid;
                float b = 0.0f, d = 0.0f;
                #pragma unroll
                for (int k = 0; k < 16; k++) {
                    b += s_pb[tid * 17 + k];
                    d += s_pd[tid * 17 + k];
                }
                float Rn = R_own / fmaxf(R_own * b, EPSF);
                g_rowdcg[i] = Rn * d / log2f((float)i + 2.0f);
            }
            grid_barrier(bid, tid);
        }
    }

    // ================= FINAL ==============================================
    if (bid == 0) {
        float part = 0.0f;
        #pragma unroll
        for (int k = 0; k < 8; k++) part += __ldcg(&g_rowdcg[tid * 8 + k]);
        part = wredsum(part);
        if (lane == 0) s_red[wid] = part;
        float ip = (tid < NBLK) ? __ldcg(&g_idcgPart[tid]) : 0.0f;
        ip = wredsum(ip);
        if (lane == 0) s_red[16 + wid] = ip;
        __syncthreads();
        if (tid == 0) {
            float dcg = 0.0f, idcg = 0.0f;
            for (int k = 0; k < 16; k++) { dcg += s_red[k]; idcg += s_red[16 + k]; }
            out[0] = -(dcg / (idcg + 1e-8f));
        }
    }
}

extern "C" void kernel_launch(void* const* d_in, const int* in_sizes, int n_in,
                              void* d_out, int out_size) {
    const float* pred   = (const float*)d_in[0];
    const float* target = (const float*)d_in[1];
    float* out = (float*)d_out;
    cudaFuncSetAttribute(ndcg_kernel, cudaFuncAttributeMaxDynamicSharedMemorySize,
                         SMEM_BYTES);
    ndcg_kernel<<<NBLK, TPB, SMEM_BYTES>>>(pred, target, out);
}